// round 15
// baseline (speedup 1.0000x reference)
#include <cuda_runtime.h>
#include <cuda_fp16.h>
#include <math.h>

#define NPIX 120
#define NANG 120
#define NK   61
#define NTHR 960

#define PSTRW 133                    // texel row stride in words
#define PROWS 128                    // rows for padded coords yi in [21,148]
#define PIMG_WORDS (PROWS * PSTRW)   // 17024 (68096 B)

#define PIMG_B  0
#define SANG_B  (PIMG_WORDS * 4)         // 68096
#define STW_B   (SANG_B + 960)
#define SOUT_B  (STW_B + 960)
#define SRED_B  (SOUT_B + 256)
#define SMEM_BYTES (SRED_B + 256)        // ~70.5 KB -> 2 CTAs/SM

// global sinogram scratch, transposed [s][a], per-batch 14400 floats
__device__ static float gsino[1024 * NANG * NPIX];

typedef unsigned long long u64;

__device__ __forceinline__ u64 pk2(float lo, float hi) {
    u64 d; asm("mov.b64 %0,{%1,%2};" : "=l"(d) : "f"(lo), "f"(hi)); return d;
}
__device__ __forceinline__ u64 fma2(u64 a, u64 b, u64 c) {
    u64 d; asm("fma.rn.f32x2 %0,%1,%2,%3;" : "=l"(d) : "l"(a), "l"(b), "l"(c)); return d;
}
__device__ __forceinline__ u64 add2(u64 a, u64 b) {
    u64 d; asm("add.rn.f32x2 %0,%1,%2;" : "=l"(d) : "l"(a), "l"(b)); return d;
}

// one bilinear fp8-quad sample at packed coords P; returns half result
__device__ __forceinline__ __half sample_one(u64 P, unsigned pb, u64 C1, u64 C2n, u64 M1) {
    u64 PM = add2(P, C1);                   // 2^23 + floor(p), bits = BIASI + idx
    u64 XI = add2(PM, C2n);                 // (xi, yi) small floats, exact
    u64 FR = fma2(XI, M1, P);               // (fx, fy) = P - XI, exact
    unsigned ixb, iyb;
    asm("mov.b64 {%0,%1},%2;" : "=r"(ixb), "=r"(iyb) : "l"(PM));
    float fx, fy;
    asm("mov.b64 {%0,%1},%2;" : "=f"(fx), "=f"(fy) : "l"(FR));
    unsigned idx  = iyb * 133u + ixb;       // bias folded into pb
    unsigned addr = pb + (idx << 2);
    unsigned quad;
    asm("ld.shared.b32 %0,[%1];" : "=r"(quad) : "r"(addr));
    unsigned topu, dvyu;
    asm("cvt.rn.f16x2.e4m3x2 %0, %1;" : "=r"(topu) : "h"((unsigned short)quad));
    asm("cvt.rn.f16x2.e4m3x2 %0, %1;" : "=r"(dvyu) : "h"((unsigned short)(quad >> 16)));
    __half2 top = *(__half2*)&topu;          // (v00, v01)
    __half2 dvy = *(__half2*)&dvyu;          // (v10-v00, v11-v01)
    unsigned fxyu;
    asm("cvt.rn.f16x2.f32 %0, %1, %2;" : "=r"(fxyu) : "f"(fy), "f"(fx)); // hi=fy lo=fx
    __half2 fxy = *(__half2*)&fxyu;
    __half2 fy2 = __half2half2(__high2half(fxy));
    __half2 m   = __hfma2(dvy, fy2, top);    // y-lerp (dv pre-stored)
    __half dm   = __hsub(__high2half(m), __low2half(m));
    return __hfma(dm, __low2half(fxy), __low2half(m)); // x-lerp
}

__global__ void __launch_bounds__(NTHR, 2)
ring_kernel(const float* __restrict__ bev, float* __restrict__ out)
{
    extern __shared__ char smraw[];
    unsigned* pimg  = (unsigned*)(smraw + PIMG_B);
    float2*   sang  = (float2*)(smraw + SANG_B);
    float2*   stw   = (float2*)(smraw + STW_B);
    float*    sout  = (float*)(smraw + SOUT_B);
    float*    sred  = (float*)(smraw + SRED_B);

    const int tid = threadIdx.x;
    const int b   = blockIdx.x;
    float* gs = gsino + b * (NANG * NPIX);

    unsigned pimg_base;
    {
        unsigned long long tmp;
        asm("cvta.to.shared.u64 %0, %1;" : "=l"(tmp) : "l"((void*)pimg));
        pimg_base = (unsigned)tmp;
    }
    const unsigned BIASI = 0x4B000000u;   // bit pattern of 2^23
    const unsigned pb = pimg_base - (BIASI * 134u + 21u * 133u + 21u) * 4u;

    // ---- Phase 0: exact trig tables (double precision, once per CTA) ----
    if (tid < NANG) {
        double th = 6.283185307179586476925287 * (double)tid / 119.0;
        double s, c;
        sincos(th, &s, &c);
        sang[tid] = make_float2((float)c, (float)s);
        double ws, wc;
        sincospi((double)tid / 60.0, &ws, &wc);
        stw[tid] = make_float2((float)wc, (float)(-ws));
    }
    if (tid < 64) sout[tid] = 0.0f;

    // ---- Phase 1: pre-differenced fp8-quad texels: (v00, v01, v10-v00, v11-v01) ----
    const float* g = bev + (long)b * (NPIX * NPIX);
    for (int i = tid; i < PROWS * PROWS; i += NTHR) {
        int ry = i >> 7;              // 0..127
        int cx = i & 127;             // 0..127
        int y = ry - 4;               // image coords [-4,123] (yi = ry+21, -25)
        int x = cx - 4;
        float v00 = 0.f, v01 = 0.f, v10 = 0.f, v11 = 0.f;
        bool y0ok = ((unsigned)y < 120u), y1ok = ((unsigned)(y + 1) < 120u);
        bool x0ok = ((unsigned)x < 120u), x1ok = ((unsigned)(x + 1) < 120u);
        if (y0ok && x0ok) v00 = __ldg(g + y * NPIX + x);
        if (y0ok && x1ok) v01 = __ldg(g + y * NPIX + x + 1);
        if (y1ok && x0ok) v10 = __ldg(g + (y + 1) * NPIX + x);
        if (y1ok && x1ok) v11 = __ldg(g + (y + 1) * NPIX + x + 1);
        float d0 = v10 - v00, d1 = v11 - v01;
        unsigned short lo, hi;
        asm("cvt.rn.satfinite.e4m3x2.f32 %0, %1, %2;" : "=h"(lo) : "f"(v01), "f"(v00));
        asm("cvt.rn.satfinite.e4m3x2.f32 %0, %1, %2;" : "=h"(hi) : "f"(d1), "f"(d0));
        pimg[ry * PSTRW + cx] = (unsigned)lo | ((unsigned)hi << 16);
    }
    __syncthreads();

    // ---- Phase 2: clipped Radon, exactly 15 rays/thread. Dual P chains for ILP ----
    const u64 C1  = pk2(8388607.5f, 8388607.5f);   // 2^23 - 0.5 (round -> floor)
    const u64 C2n = pk2(-8388608.0f, -8388608.0f); // -2^23
    const u64 M1  = pk2(-1.0f, -1.0f);
    for (int p = tid; p < NANG * NPIX; p += NTHR) {
        int a  = p / NPIX;
        int si = p - a * NPIX;
        float2 cs = sang[a];
        float ct = cs.x, st = cs.y;
        float sv = (float)si - 59.5f;
        float px0 = fmaf(sv, ct, fmaf(59.5f, st, 84.5f));
        float py0 = fmaf(sv, st, fmaf(-59.5f, ct, 84.5f));
        float dx = -st, dy = ct;

        // clip to nonzero-texel region: px,py in (23.5, 145.5)
        float t0 = 0.0f, t1 = 119.0f;
        if (fabsf(dx) > 1e-9f) {
            float inv = __fdividef(1.0f, dx);
            float A = (23.5f - px0) * inv, B = (145.5f - px0) * inv;
            t0 = fmaxf(t0, fminf(A, B));
            t1 = fminf(t1, fmaxf(A, B));
        } else if (px0 < 23.5f || px0 > 145.5f) t1 = -5.0f;
        if (fabsf(dy) > 1e-9f) {
            float inv = __fdividef(1.0f, dy);
            float A = (23.5f - py0) * inv, B = (145.5f - py0) * inv;
            t0 = fmaxf(t0, fminf(A, B));
            t1 = fminf(t1, fmaxf(A, B));
        } else if (py0 < 23.5f || py0 > 145.5f) t1 = -5.0f;
        t0 = fminf(t0, 126.0f);
        t1 = fmaxf(t1, -6.0f);
        int ta = max(0, (int)t0);            // out-of-zone taps are exact zeros
        int tb = min(119, (int)t1 + 1);

        float acc = 0.0f;
        u64 D  = pk2(dx, dy);
        u64 D2 = add2(D, D);                 // exact (doubling)
        u64 PA = fma2(pk2((float)ta, (float)ta), D, pk2(px0, py0));
        u64 PB = add2(PA, D);
        int t = ta;
        #pragma unroll 2
        for (; t + 1 <= tb; t += 2) {
            __half rrA = sample_one(PA, pb, C1, C2n, M1);
            __half rrB = sample_one(PB, pb, C1, C2n, M1);
            PA = add2(PA, D2);               // independent chains
            PB = add2(PB, D2);
            acc += __half2float(__hadd(rrA, rrB));
        }
        if (t <= tb) {
            acc += __half2float(sample_one(PA, pb, C1, C2n, M1));
        }
        gs[si * NPIX + a] = acc;    // transposed scatter to gmem scratch
    }
    __syncthreads();

    // ---- Phase 3: folded real DFT, 2 angles per task via float2 loads ----
    for (int it = tid; it < NK * 60; it += NTHR) {
        int k = it / 60;
        int j = it - k * 60;              // angle pair (2j, 2j+1)
        const float2* v = (const float2*)(gs + 2 * j);
        float2 x0  = v[0];
        float2 x60 = v[60 * 60];
        float sgn = (k & 1) ? -1.0f : 1.0f;
        float re0 = fmaf(sgn, x60.x, x0.x);
        float re1 = fmaf(sgn, x60.y, x0.y);
        float im0 = 0.0f, im1 = 0.0f;
        int m = k;
        #pragma unroll 4
        for (int n = 1; n <= 59; n++) {
            float2 xa = v[n * 60];
            float2 xb = v[(NPIX - n) * 60];
            float2 w = stw[m];
            re0 = fmaf(xa.x + xb.x, w.x, re0);
            im0 = fmaf(xa.x - xb.x, w.y, im0);
            re1 = fmaf(xa.y + xb.y, w.x, re1);
            im1 = fmaf(xa.y - xb.y, w.y, im1);
            m += k;
            if (m >= NANG) m -= NANG;
        }
        float mag0 = sqrtf(fmaf(re0, re0, im0 * im0) * (1.0f / 120.0f) + 1e-15f);
        float mag1 = sqrtf(fmaf(re1, re1, im1 * im1) * (1.0f / 120.0f) + 1e-15f);
        atomicAdd(&sout[k], mag0 + mag1);
    }
    __syncthreads();

    // ---- Phase 4: L2 norm over mirrored 120-vector, write ----
    if (tid < NK) {
        float v = sout[tid];
        float w = (tid == 0 || tid == 60) ? 1.0f : 2.0f;
        sred[tid] = w * v * v;
    }
    __syncthreads();
    if (tid == 0) {
        float s = 0.0f;
        for (int i = 0; i < NK; i++) s += sred[i];
        sred[63] = fmaxf(sqrtf(s), 1e-12f);
    }
    __syncthreads();
    float inv = 1.0f / sred[63];
    for (int k = tid; k < NPIX; k += NTHR) {
        int kk = (k <= 60) ? k : (NPIX - k);
        out[(long)b * NPIX + k] = sout[kk] * inv;
    }
}

extern "C" void kernel_launch(void* const* d_in, const int* in_sizes, int n_in,
                              void* d_out, int out_size)
{
    const float* bev = (const float*)d_in[0];
    float* out = (float*)d_out;
    int B = in_sizes[0] / (NPIX * NPIX);   // 1024

    cudaFuncSetAttribute(ring_kernel,
                         cudaFuncAttributeMaxDynamicSharedMemorySize, SMEM_BYTES);
    ring_kernel<<<B, NTHR, SMEM_BYTES>>>(bev, out);
}

// round 16
// speedup vs baseline: 1.0798x; 1.0798x over previous
#include <cuda_runtime.h>
#include <cuda_fp16.h>
#include <math.h>

#define NPIX 120
#define NANG 120
#define NK   61
#define NTHR 1024

#define PSTRW 133                    // texel row stride in words
#define PROWS 128                    // rows for padded coords yi in [21,148]
#define PIMG_WORDS (PROWS * PSTRW)   // 17024 (68096 B)
#define SSTRH 122                    // fp16 sinogram row stride in halves (61 half2/row)

#define PIMG_B  0
#define SSINO_B (PIMG_WORDS * 4)         // 68096
#define SANG_B  (SSINO_B + NPIX*SSTRH*2) // 68096 + 29280 = 97376
#define STW_B   (SANG_B + 960)
#define SOUT_B  (STW_B + 960)
#define SRED_B  (SOUT_B + 256)
#define SMEM_BYTES (SRED_B + 256)        // 99808 B -> 2 CTAs/SM

typedef unsigned long long u64;

__device__ __forceinline__ u64 pk2(float lo, float hi) {
    u64 d; asm("mov.b64 %0,{%1,%2};" : "=l"(d) : "f"(lo), "f"(hi)); return d;
}
__device__ __forceinline__ u64 fma2(u64 a, u64 b, u64 c) {
    u64 d; asm("fma.rn.f32x2 %0,%1,%2,%3;" : "=l"(d) : "l"(a), "l"(b), "l"(c)); return d;
}
__device__ __forceinline__ u64 add2(u64 a, u64 b) {
    u64 d; asm("add.rn.f32x2 %0,%1,%2;" : "=l"(d) : "l"(a), "l"(b)); return d;
}

// one bilinear fp8-quad sample at packed coords P; returns half result
__device__ __forceinline__ __half sample_one(u64 P, unsigned pb, u64 C1, u64 C2n, u64 M1) {
    u64 PM = add2(P, C1);                   // 2^23 + floor(p), bits = BIASI + idx
    u64 XI = add2(PM, C2n);                 // (xi, yi) small floats, exact
    u64 FR = fma2(XI, M1, P);               // (fx, fy) = P - XI, exact
    unsigned ixb, iyb;
    asm("mov.b64 {%0,%1},%2;" : "=r"(ixb), "=r"(iyb) : "l"(PM));
    float fx, fy;
    asm("mov.b64 {%0,%1},%2;" : "=f"(fx), "=f"(fy) : "l"(FR));
    unsigned idx  = iyb * 133u + ixb;       // bias folded into pb
    unsigned addr = pb + (idx << 2);
    unsigned quad;
    asm("ld.shared.b32 %0,[%1];" : "=r"(quad) : "r"(addr));
    unsigned topu, dvyu;
    asm("cvt.rn.f16x2.e4m3x2 %0, %1;" : "=r"(topu) : "h"((unsigned short)quad));
    asm("cvt.rn.f16x2.e4m3x2 %0, %1;" : "=r"(dvyu) : "h"((unsigned short)(quad >> 16)));
    __half2 top = *(__half2*)&topu;          // (v00, v01)
    __half2 dvy = *(__half2*)&dvyu;          // (v10-v00, v11-v01)
    unsigned fxyu;
    asm("cvt.rn.f16x2.f32 %0, %1, %2;" : "=r"(fxyu) : "f"(fy), "f"(fx)); // hi=fy lo=fx
    __half2 fxy = *(__half2*)&fxyu;
    __half2 fy2 = __half2half2(__high2half(fxy));
    __half2 m   = __hfma2(dvy, fy2, top);    // y-lerp (dv pre-stored)
    __half dm   = __hsub(__high2half(m), __low2half(m));
    return __hfma(dm, __low2half(fxy), __low2half(m)); // x-lerp
}

__global__ void __launch_bounds__(NTHR, 2)
ring_kernel(const float* __restrict__ bev, float* __restrict__ out)
{
    extern __shared__ char smraw[];
    unsigned* pimg   = (unsigned*)(smraw + PIMG_B);
    __half*   ssinoh = (__half*)(smraw + SSINO_B);     // [s][a], fp16, stride SSTRH
    float2*   sang   = (float2*)(smraw + SANG_B);
    float2*   stw    = (float2*)(smraw + STW_B);
    float*    sout   = (float*)(smraw + SOUT_B);
    float*    sred   = (float*)(smraw + SRED_B);

    const int tid = threadIdx.x;
    const int b   = blockIdx.x;

    unsigned pimg_base;
    {
        unsigned long long tmp;
        asm("cvta.to.shared.u64 %0, %1;" : "=l"(tmp) : "l"((void*)pimg));
        pimg_base = (unsigned)tmp;
    }
    const unsigned BIASI = 0x4B000000u;   // bit pattern of 2^23
    const unsigned pb = pimg_base - (BIASI * 134u + 21u * 133u + 21u) * 4u;

    // ---- Phase 0: exact trig tables (double precision, once per CTA) ----
    if (tid < NANG) {
        double th = 6.283185307179586476925287 * (double)tid / 119.0;
        double s, c;
        sincos(th, &s, &c);
        sang[tid] = make_float2((float)c, (float)s);
        double ws, wc;
        sincospi((double)tid / 60.0, &ws, &wc);
        stw[tid] = make_float2((float)wc, (float)(-ws));
    }
    if (tid < 64) sout[tid] = 0.0f;

    // ---- Phase 1: pre-differenced fp8-quad texels: (v00, v01, v10-v00, v11-v01) ----
    const float* g = bev + (long)b * (NPIX * NPIX);
    for (int i = tid; i < PROWS * PROWS; i += NTHR) {
        int ry = i >> 7;              // 0..127
        int cx = i & 127;             // 0..127
        int y = ry - 4;               // image coords [-4,123] (yi = ry+21, -25)
        int x = cx - 4;
        float v00 = 0.f, v01 = 0.f, v10 = 0.f, v11 = 0.f;
        bool y0ok = ((unsigned)y < 120u), y1ok = ((unsigned)(y + 1) < 120u);
        bool x0ok = ((unsigned)x < 120u), x1ok = ((unsigned)(x + 1) < 120u);
        if (y0ok && x0ok) v00 = __ldg(g + y * NPIX + x);
        if (y0ok && x1ok) v01 = __ldg(g + y * NPIX + x + 1);
        if (y1ok && x0ok) v10 = __ldg(g + (y + 1) * NPIX + x);
        if (y1ok && x1ok) v11 = __ldg(g + (y + 1) * NPIX + x + 1);
        float d0 = v10 - v00, d1 = v11 - v01;
        unsigned short lo, hi;
        asm("cvt.rn.satfinite.e4m3x2.f32 %0, %1, %2;" : "=h"(lo) : "f"(v01), "f"(v00));
        asm("cvt.rn.satfinite.e4m3x2.f32 %0, %1, %2;" : "=h"(hi) : "f"(d1), "f"(d0));
        pimg[ry * PSTRW + cx] = (unsigned)lo | ((unsigned)hi << 16);
    }
    __syncthreads();

    // ---- Phase 2: clipped Radon. 1 LDS.32/sample; fp16 sinogram store to SMEM ----
    const u64 C1  = pk2(8388607.5f, 8388607.5f);   // 2^23 - 0.5 (round -> floor)
    const u64 C2n = pk2(-8388608.0f, -8388608.0f); // -2^23
    const u64 M1  = pk2(-1.0f, -1.0f);
    for (int p = tid; p < NANG * NPIX; p += NTHR) {
        int a  = p / NPIX;
        int si = p - a * NPIX;
        float2 cs = sang[a];
        float ct = cs.x, st = cs.y;
        float sv = (float)si - 59.5f;
        float px0 = fmaf(sv, ct, fmaf(59.5f, st, 84.5f));
        float py0 = fmaf(sv, st, fmaf(-59.5f, ct, 84.5f));
        float dx = -st, dy = ct;

        // clip to nonzero-texel region: px,py in (23.5, 145.5)
        float t0 = 0.0f, t1 = 119.0f;
        if (fabsf(dx) > 1e-9f) {
            float inv = __fdividef(1.0f, dx);
            float A = (23.5f - px0) * inv, B = (145.5f - px0) * inv;
            t0 = fmaxf(t0, fminf(A, B));
            t1 = fminf(t1, fmaxf(A, B));
        } else if (px0 < 23.5f || px0 > 145.5f) t1 = -5.0f;
        if (fabsf(dy) > 1e-9f) {
            float inv = __fdividef(1.0f, dy);
            float A = (23.5f - py0) * inv, B = (145.5f - py0) * inv;
            t0 = fmaxf(t0, fminf(A, B));
            t1 = fminf(t1, fmaxf(A, B));
        } else if (py0 < 23.5f || py0 > 145.5f) t1 = -5.0f;
        t0 = fminf(t0, 126.0f);
        t1 = fmaxf(t1, -6.0f);
        int ta = max(0, (int)t0);            // out-of-zone taps are exact zeros
        int tb = min(119, (int)t1 + 1);

        float acc = 0.0f;
        u64 D = pk2(dx, dy);
        u64 P = fma2(pk2((float)ta, (float)ta), D, pk2(px0, py0));
        int t = ta;
        #pragma unroll 2
        for (; t + 1 <= tb; t += 2) {
            __half rrA = sample_one(P, pb, C1, C2n, M1);
            u64 P1 = add2(P, D);
            __half rrB = sample_one(P1, pb, C1, C2n, M1);
            P = add2(P1, D);
            acc += __half2float(__hadd(rrA, rrB));
        }
        if (t <= tb) {
            acc += __half2float(sample_one(P, pb, C1, C2n, M1));
        }
        ssinoh[si * SSTRH + a] = __float2half_rn(acc);   // fp16 SMEM store
    }
    __syncthreads();

    // ---- Phase 3: folded real DFT, 2 angles per task via half2 SMEM loads ----
    const __half2* sb = (const __half2*)(smraw + SSINO_B);   // 61 half2 per row
    for (int it = tid; it < NK * 60; it += NTHR) {
        int k = it / 60;
        int j = it - k * 60;              // angle pair (2j, 2j+1)
        float2 x0  = __half22float2(sb[j]);
        float2 x60 = __half22float2(sb[60 * 61 + j]);
        float sgn = (k & 1) ? -1.0f : 1.0f;
        float re0 = fmaf(sgn, x60.x, x0.x);
        float re1 = fmaf(sgn, x60.y, x0.y);
        float im0 = 0.0f, im1 = 0.0f;
        int m = k;
        #pragma unroll 4
        for (int n = 1; n <= 59; n++) {
            float2 xa = __half22float2(sb[n * 61 + j]);
            float2 xb = __half22float2(sb[(NPIX - n) * 61 + j]);
            float2 w = stw[m];
            re0 = fmaf(xa.x + xb.x, w.x, re0);
            im0 = fmaf(xa.x - xb.x, w.y, im0);
            re1 = fmaf(xa.y + xb.y, w.x, re1);
            im1 = fmaf(xa.y - xb.y, w.y, im1);
            m += k;
            if (m >= NANG) m -= NANG;
        }
        float mag0 = sqrtf(fmaf(re0, re0, im0 * im0) * (1.0f / 120.0f) + 1e-15f);
        float mag1 = sqrtf(fmaf(re1, re1, im1 * im1) * (1.0f / 120.0f) + 1e-15f);
        atomicAdd(&sout[k], mag0 + mag1);
    }
    __syncthreads();

    // ---- Phase 4: L2 norm over mirrored 120-vector, write ----
    if (tid < NK) {
        float v = sout[tid];
        float w = (tid == 0 || tid == 60) ? 1.0f : 2.0f;
        sred[tid] = w * v * v;
    }
    __syncthreads();
    if (tid == 0) {
        float s = 0.0f;
        for (int i = 0; i < NK; i++) s += sred[i];
        sred[63] = fmaxf(sqrtf(s), 1e-12f);
    }
    __syncthreads();
    float inv = 1.0f / sred[63];
    for (int k = tid; k < NPIX; k += NTHR) {
        int kk = (k <= 60) ? k : (NPIX - k);
        out[(long)b * NPIX + k] = sout[kk] * inv;
    }
}

extern "C" void kernel_launch(void* const* d_in, const int* in_sizes, int n_in,
                              void* d_out, int out_size)
{
    const float* bev = (const float*)d_in[0];
    float* out = (float*)d_out;
    int B = in_sizes[0] / (NPIX * NPIX);   // 1024

    cudaFuncSetAttribute(ring_kernel,
                         cudaFuncAttributeMaxDynamicSharedMemorySize, SMEM_BYTES);
    ring_kernel<<<B, NTHR, SMEM_BYTES>>>(bev, out);
}